// round 15
// baseline (speedup 1.0000x reference)
#include <cuda_runtime.h>
#include <cuda_bf16.h>

// Gridding R13: same scheme as R12 (parity-grid scratch, 2 v4 REDs/point,
// sliding-window dense-float2 remap), but 4 phases x 8 batches with a 32MB
// scratch so scratch + streamed points fit L2 -> no DRAM RMW / DRAM remap.

#define GRID_S    32
#define GRID_G    64
#define NPTS_LOG2 18
#define NB_PHASE  8
#define NPHASE    4
#define PCHUNK    8          // p-values per remap thread
#define NCHUNK    4          // 32 / PCHUNK

// 4 grids x 8 batches x 2^18 floats = 32 MB scratch (reused across phases)
__device__ float g_scratch[4 * NB_PHASE * (1 << NPTS_LOG2)];

__device__ __forceinline__ void red_v4(float* p, float a, float b, float c, float d) {
    asm volatile("red.global.add.v4.f32 [%0], {%1, %2, %3, %4};"
                 :: "l"(p), "f"(a), "f"(b), "f"(c), "f"(d) : "memory");
}

__global__ __launch_bounds__(256)
void gridding_scatter_kernel(const float* __restrict__ pt,
                             float* __restrict__ scratch, int npts_phase)
{
    int i = blockIdx.x * blockDim.x + threadIdx.x;
    if (i >= npts_phase) return;

    // evict-first: points are read once; keep L2 for the scratch grids
    float x = __ldcs(&pt[3 * i + 0]) * (float)GRID_S;
    float y = __ldcs(&pt[3 * i + 1]) * (float)GRID_S;
    float z = __ldcs(&pt[3 * i + 2]) * (float)GRID_S;

    // drop points whose scaled coord-sum is exactly 0 (x32 scaling is exact)
    float m = ((x + y + z) != 0.0f) ? 1.0f : 0.0f;

    float fx = floorf(x), fy = floorf(y), fz = floorf(z);
    float dx = x - fx, dy = y - fy, dz = z - fz;   // fractions from UNCLIPPED floor

    int ix = min(max(__float2int_rn(fx) + GRID_S, 0), GRID_G - 2);
    int iy = min(max(__float2int_rn(fy) + GRID_S, 0), GRID_G - 2);
    int iz = min(max(__float2int_rn(fz) + GRID_S, 0), GRID_G - 2);

    float wx0 = (1.0f - dx) * m;
    float wx1 = dx * m;
    float wy0 = 1.0f - dy, wy1 = dy;
    float wz0 = 1.0f - dz, wz1 = dz;

    int b   = i >> NPTS_LOG2;            // batch-local within phase, [0,8)
    int phi = iy & 1;
    int zb  = iz & 1;
    int p   = iy >> 1;

    int gidx = phi * 2 + zb;
    int pos  = (ix << 12) + (p << 7) + 2 * (iz & ~1);          // 16B aligned
    float* base = scratch + ((gidx * NB_PHASE + b) << NPTS_LOG2) + pos;

    // lanes: {(y0,z0), (y1,z0), (y0,z1), (y1,z1)}
    float a0 = wy0 * wz0, a1 = wy1 * wz0, a2 = wy0 * wz1, a3 = wy1 * wz1;
    red_v4(base,        wx0 * a0, wx0 * a1, wx0 * a2, wx0 * a3);
    red_v4(base + 4096, wx1 * a0, wx1 * a1, wx1 * a2, wx1 * a3);   // x+1
}

// Sliding-window remap (see R12): thread = (b, x, z, chunk h); loops p
// producing outputs y=2p, 2p+1 at fixed (x,z) with dense float2 loads.
__global__ __launch_bounds__(256)
void gridding_remap_kernel(float* __restrict__ out,
                           const float* __restrict__ scratch)
{
    int t = blockIdx.x * blockDim.x + threadIdx.x;
    int z = t & 63;
    int x = (t >> 6) & 63;
    int h = (t >> 12) & (NCHUNK - 1);
    int b = t >> 14;                     // [0, NB_PHASE)

    const float* g0 = scratch + ((0 * NB_PHASE + b) << NPTS_LOG2) + (x << 12);
    const float* g1 = scratch + ((1 * NB_PHASE + b) << NPTS_LOG2) + (x << 12);
    const float* g2 = scratch + ((2 * NB_PHASE + b) << NPTS_LOG2) + (x << 12);
    const float* g3 = scratch + ((3 * NB_PHASE + b) << NPTS_LOG2) + (x << 12);

    int qA = 2 * z;
    int qB = (z >= 1) ? (2 * z - 2) : 126;   // slots 126/127 never written (zero)

    int p0 = h * PCHUNK;
    float2 Cp, Dp;
    if (p0 == 0) {
        Cp = make_float2(0.f, 0.f);
        Dp = make_float2(0.f, 0.f);
    } else {
        Cp = *(const float2*)&g2[((p0 - 1) << 7) + qA];
        Dp = *(const float2*)&g3[((p0 - 1) << 7) + qB];
    }

    float* o = out + (b << NPTS_LOG2) + (x << 12) + z;

    #pragma unroll
    for (int p = p0; p < p0 + PCHUNK; p++) {
        float2 A = *(const float2*)&g0[(p << 7) + qA];
        float2 B = *(const float2*)&g1[(p << 7) + qB];
        float2 C = *(const float2*)&g2[(p << 7) + qA];
        float2 D = *(const float2*)&g3[(p << 7) + qB];

        float o0 = A.x + B.x + Cp.y + Dp.y;   // y = 2p
        float o1 = A.y + B.y + C.x  + D.x;    // y = 2p+1
        o[(2 * p)     << 6] = o0;
        o[(2 * p + 1) << 6] = o1;

        Cp = C;  Dp = D;
    }
}

extern "C" void kernel_launch(void* const* d_in, const int* in_sizes, int n_in,
                              void* d_out, int out_size)
{
    const float* ptcloud = (const float*)d_in[0];
    float* out = (float*)d_out;

    int total_pts = in_sizes[0] / 3;            // 32 * 262144
    int pts_phase = total_pts / NPHASE;         // 8 * 262144
    int out_phase = out_size / NPHASE;          // 8 * 262144

    void* scratch_ptr = nullptr;
    cudaGetSymbolAddress(&scratch_ptr, g_scratch);

    const int threads = 256;
    int sblocks = (pts_phase + threads - 1) / threads;
    // remap threads: NB_PHASE * 64(x) * 64(z) * NCHUNK
    int rthreads = NB_PHASE * 64 * 64 * NCHUNK;
    int rblocks = rthreads / threads;

    for (int ph = 0; ph < NPHASE; ph++) {
        cudaMemsetAsync(scratch_ptr, 0, sizeof(g_scratch), 0);
        gridding_scatter_kernel<<<sblocks, threads>>>(
            ptcloud + (size_t)ph * pts_phase * 3, (float*)scratch_ptr, pts_phase);
        gridding_remap_kernel<<<rblocks, threads>>>(
            out + (size_t)ph * out_phase, (const float*)scratch_ptr);
    }
}

// round 17
// speedup vs baseline: 1.2857x; 1.2857x over previous
#include <cuda_runtime.h>
#include <cuda_fp16.h>

// Gridding R15: single red.global.add.noftz.v4.f16x2 per point (8 corner
// weights as 8 contiguous fp16 = 16B). 8 parity grids (ix&1, iy&1, iz&1),
// slot layout (P,p,q=2z+cy,xc) with xc innermost. Remap = R12 sliding window
// extended to X-pairs so both xc halves of every 8B load are consumed.
// 2 phases x 16 batches, 64MB scratch (same bytes as R12; fp16 halves it,
// 8 grids double it back).

#define GRID_S    32
#define GRID_G    64
#define NPTS_LOG2 18
#define NB_PHASE  16
#define NPHASE    2
#define PCHUNK    4
#define NCHUNK    8

// 8 grids x 16 batches x 2^18 halfs = 64 MB
__device__ __half g_scratch[(size_t)8 * NB_PHASE * (1 << 18)];

__device__ __forceinline__ void red_v4_h2(__half* p, __half2 a, __half2 b,
                                          __half2 c, __half2 d) {
    unsigned ra = *reinterpret_cast<unsigned*>(&a);
    unsigned rb = *reinterpret_cast<unsigned*>(&b);
    unsigned rc = *reinterpret_cast<unsigned*>(&c);
    unsigned rd = *reinterpret_cast<unsigned*>(&d);
    asm volatile("red.global.add.noftz.v4.f16x2 [%0], {%1, %2, %3, %4};"
                 :: "l"(p), "r"(ra), "r"(rb), "r"(rc), "r"(rd) : "memory");
}

__global__ __launch_bounds__(256)
void gridding_scatter_kernel(const float* __restrict__ pt, int npts_phase)
{
    int i = blockIdx.x * blockDim.x + threadIdx.x;
    if (i >= npts_phase) return;

    float x = __ldcs(&pt[3 * i + 0]) * (float)GRID_S;
    float y = __ldcs(&pt[3 * i + 1]) * (float)GRID_S;
    float z = __ldcs(&pt[3 * i + 2]) * (float)GRID_S;

    // drop points whose scaled coord-sum is exactly 0 (x32 scaling is exact)
    float m = ((x + y + z) != 0.0f) ? 1.0f : 0.0f;

    float fx = floorf(x), fy = floorf(y), fz = floorf(z);
    float dx = x - fx, dy = y - fy, dz = z - fz;   // fractions from UNCLIPPED floor

    int ix = min(max(__float2int_rn(fx) + GRID_S, 0), GRID_G - 2);
    int iy = min(max(__float2int_rn(fy) + GRID_S, 0), GRID_G - 2);
    int iz = min(max(__float2int_rn(fz) + GRID_S, 0), GRID_G - 2);

    float wx0 = (1.0f - dx) * m;
    float wx1 = dx * m;
    float wy0 = 1.0f - dy, wy1 = dy;
    float wz0 = 1.0f - dz, wz1 = dz;

    int b   = i >> NPTS_LOG2;            // batch-local within phase, [0,16)
    int xa  = ix & 1, P = ix >> 1;
    int phi = iy & 1, p = iy >> 1;
    int zb  = iz & 1;
    int q0  = 2 * (iz & ~1);             // q-block base (q = 2z+cy, zb-shifted)

    int g = (xa << 2) | (phi << 1) | zb;
    size_t base = (((size_t)(g * NB_PHASE + b)) << 18)
                + ((size_t)P << 13) + (p << 8) + (q0 << 1);   // 16B aligned

    // corner weights, q-major / xc-minor:
    // (q0+k, xc): k=0:(z0,cy0) k=1:(z0,cy1) k=2:(z1,cy0) k=3:(z1,cy1)
    float a0 = wy0 * wz0, a1 = wy1 * wz0, a2 = wy0 * wz1, a3 = wy1 * wz1;
    __half2 h0 = __floats2half2_rn(wx0 * a0, wx1 * a0);
    __half2 h1 = __floats2half2_rn(wx0 * a1, wx1 * a1);
    __half2 h2 = __floats2half2_rn(wx0 * a2, wx1 * a2);
    __half2 h3 = __floats2half2_rn(wx0 * a3, wx1 * a3);

    red_v4_h2(&g_scratch[base], h0, h1, h2, h3);
}

// load 4 halfs (8B) -> float4 {h0,h1,h2,h3} = {(q,xc0),(q,xc1),(q+1,xc0),(q+1,xc1)}
__device__ __forceinline__ float4 ld4h(const __half* p)
{
    uint2 v = *(const uint2*)p;
    __half2 lo = *reinterpret_cast<__half2*>(&v.x);
    __half2 hi = *reinterpret_cast<__half2*>(&v.y);
    float2 f0 = __half22float2(lo);
    float2 f1 = __half22float2(hi);
    return make_float4(f0.x, f0.y, f1.x, f1.y);
}

// Remap: thread = (b, U, z, h); produces X in {2U, 2U+1}, y in {2p, 2p+1}
// for p in [h*PCHUNK, h*PCHUNK+PCHUNK).
__global__ __launch_bounds__(256)
void gridding_remap_kernel(float* __restrict__ out)
{
    int t = blockIdx.x * blockDim.x + threadIdx.x;
    int z = t & 63;
    int U = (t >> 6) & 31;
    int h = (t >> 11) & (NCHUNK - 1);
    int b = t >> 14;                     // [0, NB_PHASE)

    // half-index offsets of the q-pair within a row (x2 for xc)
    int qA2 = (2 * z) << 1;
    int qB2 = ((z >= 1) ? (2 * z - 2) : 126) << 1;   // 126/127 never written

    // grid row base pointers at brick P=U (grid id = (xa<<2)|(phi<<1)|zb)
    const __half* gr[8];
    #pragma unroll
    for (int g = 0; g < 8; g++)
        gr[g] = g_scratch + (((size_t)(g * NB_PHASE + b)) << 18)
                          + ((size_t)U << 13);
    bool u0 = (U == 0);
    const float4 Z4 = make_float4(0.f, 0.f, 0.f, 0.f);

    int p0 = h * PCHUNK;

    // prev-row (p0-1) state for phi=1 grids (cy=1 halves feed y=2p)
    float4 Pc0[2], Pc1[2], Pc2[2];
    #pragma unroll
    for (int zb = 0; zb < 2; zb++) {
        int q2 = zb ? qB2 : qA2;
        if (p0 == 0) {
            Pc0[zb] = Z4;  Pc1[zb] = Z4;  Pc2[zb] = Z4;
        } else {
            int row = (p0 - 1) << 8;
            Pc0[zb] = ld4h(gr[(0 << 2) | 2 | zb] + row + q2);
            Pc1[zb] = ld4h(gr[(1 << 2) | 2 | zb] + row + q2);
            Pc2[zb] = u0 ? Z4 : ld4h(gr[(1 << 2) | 2 | zb] - (1 << 13) + row + q2);
        }
    }

    float* o = out + ((size_t)b << NPTS_LOG2) + ((size_t)(2 * U) << 12) + z;

    #pragma unroll
    for (int p = p0; p < p0 + PCHUNK; p++) {
        float o00 = 0.f, o10 = 0.f, o01 = 0.f, o11 = 0.f;
        int row = p << 8;

        #pragma unroll
        for (int zb = 0; zb < 2; zb++) {
            int q2 = zb ? qB2 : qA2;

            // phi=0 grids: cy0 -> y=2p, cy1 -> y=2p+1
            float4 A0 = ld4h(gr[zb] + row + q2);                           // xa=0,P=U
            float4 A1 = ld4h(gr[4 | zb] + row + q2);                       // xa=1,P=U
            float4 A2 = u0 ? Z4 : ld4h(gr[4 | zb] - (1 << 13) + row + q2); // xa=1,P=U-1
            o00 += A0.x + A2.y;
            o10 += A0.y + A1.x;
            o01 += A0.z + A2.w;
            o11 += A0.w + A1.z;

            // phi=1 grids: cy0 -> y=2p+1 (current), cy1 -> y=2p+2 (next step)
            float4 C0 = ld4h(gr[2 | zb] + row + q2);                       // xa=0,P=U
            float4 C1 = ld4h(gr[6 | zb] + row + q2);                       // xa=1,P=U
            float4 C2 = u0 ? Z4 : ld4h(gr[6 | zb] - (1 << 13) + row + q2); // xa=1,P=U-1
            o01 += C0.x + C2.y;
            o11 += C0.y + C1.x;
            o00 += Pc0[zb].z + Pc2[zb].w;    // prev cy1 -> y=2p
            o10 += Pc0[zb].w + Pc1[zb].z;
            Pc0[zb] = C0;  Pc1[zb] = C1;  Pc2[zb] = C2;
        }

        o[(2 * p)     << 6]          = o00;   // X=2U,   y=2p
        o[(2 * p + 1) << 6]          = o01;   // X=2U,   y=2p+1
        o[((2 * p)     << 6) + 4096] = o10;   // X=2U+1, y=2p
        o[((2 * p + 1) << 6) + 4096] = o11;   // X=2U+1, y=2p+1
    }
}

extern "C" void kernel_launch(void* const* d_in, const int* in_sizes, int n_in,
                              void* d_out, int out_size)
{
    const float* ptcloud = (const float*)d_in[0];
    float* out = (float*)d_out;

    int total_pts = in_sizes[0] / 3;            // 32 * 262144
    int pts_phase = total_pts / NPHASE;         // 16 * 262144
    int out_phase = out_size / NPHASE;          // 16 * 262144

    void* scratch_ptr = nullptr;
    cudaGetSymbolAddress(&scratch_ptr, g_scratch);
    size_t scratch_bytes = (size_t)8 * NB_PHASE * (1 << 18) * sizeof(__half);

    const int threads = 256;
    int sblocks = (pts_phase + threads - 1) / threads;
    int rthreads = NB_PHASE * 32 * 64 * NCHUNK;          // 262144
    int rblocks = rthreads / threads;                    // 1024

    for (int ph = 0; ph < NPHASE; ph++) {
        cudaMemsetAsync(scratch_ptr, 0, scratch_bytes, 0);
        gridding_scatter_kernel<<<sblocks, threads>>>(
            ptcloud + (size_t)ph * pts_phase * 3, pts_phase);
        gridding_remap_kernel<<<rblocks, threads>>>(
            out + (size_t)ph * out_phase);
    }
}